// round 1
// baseline (speedup 1.0000x reference)
#include <cuda_runtime.h>
#include <cuda_bf16.h>
#include <cstdint>

// Problem constants
#define BB 4096
#define SS 31
#define CC 512
#define HH 8
#define HD 64
#define M_TOT (BB*SS)        // 126976
#define NPOS (SS*SS)         // 961
#define BH (BB*HH)           // 32768
#define EPS 1e-5f
#define INV_SQRT_C 0.044194173824159216f   // 1/sqrt(512)

// ---------------- scratch (static device memory; no allocations) ----------------
__device__ __align__(16) float g_q[(size_t)M_TOT*CC];
__device__ __align__(16) float g_k[(size_t)M_TOT*CC];
__device__ __align__(16) float g_v[(size_t)M_TOT*CC];
__device__ __align__(16) float g_ctx[(size_t)M_TOT*CC];
__device__ __align__(16) float g_energy[(size_t)BH*NPOS];

__device__ __align__(16) float g_ch_sum[CC];
__device__ __align__(16) float g_ch_sq[CC];
__device__ __align__(16) float g_scale[CC];
__device__ __align__(16) float g_shift[CC];
__device__ __align__(16) float g_p_sum[NPOS];
__device__ __align__(16) float g_p_sq[NPOS];
__device__ __align__(16) float g_sc2[NPOS];
__device__ __align__(16) float g_sh2[NPOS];

// ---------------- packed f32x2 FMA helpers (FFMA2 on sm_103a) ----------------
__device__ __forceinline__ void ffma2(unsigned long long& acc,
                                      unsigned long long a,
                                      unsigned long long b) {
    asm("fma.rn.f32x2 %0, %1, %2, %0;" : "+l"(acc) : "l"(a), "l"(b));
}
__device__ __forceinline__ unsigned long long pack2(float x, float y) {
    unsigned long long r;
    asm("mov.b64 %0, {%1, %2};" : "=l"(r) : "f"(x), "f"(y));
    return r;
}
__device__ __forceinline__ float2 unpack2(unsigned long long v) {
    float2 r;
    asm("mov.b64 {%0, %1}, %2;" : "=f"(r.x), "=f"(r.y) : "l"(v));
    return r;
}

// ---------------- kernel: zero the reduction buffers ----------------
__global__ void k_zero() {
    int i = threadIdx.x;  // <<<1, 1024>>>
    if (i < CC)   { g_ch_sum[i] = 0.f; g_ch_sq[i] = 0.f; }
    if (i < NPOS) { g_p_sum[i] = 0.f;  g_p_sq[i] = 0.f; }
}

// ---------------- kernel: BN1 channel stats (over B*S rows) ----------------
// grid 992 blocks x 256 threads; each block handles 128 rows.
__global__ void __launch_bounds__(256) k_bn1_stats(const float* __restrict__ x) {
    const int tid = threadIdx.x;
    const size_t r0 = (size_t)blockIdx.x * 128;
    const float* xp = x + r0 * CC;
    float s0 = 0.f, s1 = 0.f, q0 = 0.f, q1 = 0.f;
    for (int r = 0; r < 128; r++) {
        float v0 = xp[(size_t)r*CC + tid];
        float v1 = xp[(size_t)r*CC + tid + 256];
        s0 += v0; q0 += v0*v0;
        s1 += v1; q1 += v1*v1;
    }
    atomicAdd(&g_ch_sum[tid],       s0);
    atomicAdd(&g_ch_sq[tid],        q0);
    atomicAdd(&g_ch_sum[tid + 256], s1);
    atomicAdd(&g_ch_sq[tid + 256],  q1);
}

__global__ void k_bn1_fin(const float* __restrict__ nw, const float* __restrict__ nb) {
    int i = blockIdx.x * blockDim.x + threadIdx.x;  // <<<2,256>>>
    if (i >= CC) return;
    float inv_n = 1.0f / (float)M_TOT;
    float mean = g_ch_sum[i] * inv_n;
    float var  = g_ch_sq[i] * inv_n - mean * mean;
    float rs   = rsqrtf(var + EPS);
    float sc   = rs * nw[i];
    g_scale[i] = sc;
    g_shift[i] = nb[i] - mean * sc;
}

// ---------------- GEMM: 128x128 tile, BK=16, f32x2 microkernel ----------------
// MODE 0: A = BN(x) on the fly; B = {Wq,Wk,Wv}; writes g_q/g_k/g_v
// MODE 1: A = g_ctx; B = Wout; epilogue adds bias + residual; writes Dout
#define BM 128
#define BN 128
#define BK 16

template<int MODE>
__global__ void __launch_bounds__(256) k_gemm(
    const float* __restrict__ Aglob,
    const float* __restrict__ W0, const float* __restrict__ W1,
    const float* __restrict__ W2,
    const float* __restrict__ bias, const float* __restrict__ resid,
    float* __restrict__ Dout)
{
    __shared__ float As[BK][BM + 4];
    __shared__ float Bs[BK][BM + 4];
    const int tid = threadIdx.x;
    const int m0 = blockIdx.y * BM;
    const int n0 = blockIdx.x * BN;

    const float* Wsel;
    float* outp;
    int ncol0;
    if (MODE == 0) {
        int nb_ = n0 >> 9;
        ncol0 = n0 & 511;
        Wsel = (nb_ == 0) ? W0 : ((nb_ == 1) ? W1 : W2);
        outp = (nb_ == 0) ? g_q : ((nb_ == 1) ? g_k : g_v);
    } else {
        Wsel = W0; outp = Dout; ncol0 = n0;
    }
    const float* Ap = (MODE == 0) ? Aglob : g_ctx;

    const int lr = tid >> 2;          // 0..63
    const int lc = (tid & 3) << 2;    // 0,4,8,12
    const int tx = tid & 15;
    const int ty = tid >> 4;

    unsigned long long acc[8][4];
#pragma unroll
    for (int i = 0; i < 8; i++)
#pragma unroll
        for (int j = 0; j < 4; j++) acc[i][j] = 0ull;

    for (int k0 = 0; k0 < CC; k0 += BK) {
#pragma unroll
        for (int rr = 0; rr < BM; rr += 64) {
            float4 xv = *(const float4*)(Ap + (size_t)(m0 + lr + rr) * CC + k0 + lc);
            if (MODE == 0) {
                float4 sc = *(const float4*)(g_scale + k0 + lc);
                float4 sh = *(const float4*)(g_shift + k0 + lc);
                As[lc + 0][lr + rr] = fmaf(xv.x, sc.x, sh.x);
                As[lc + 1][lr + rr] = fmaf(xv.y, sc.y, sh.y);
                As[lc + 2][lr + rr] = fmaf(xv.z, sc.z, sh.z);
                As[lc + 3][lr + rr] = fmaf(xv.w, sc.w, sh.w);
            } else {
                As[lc + 0][lr + rr] = xv.x;
                As[lc + 1][lr + rr] = xv.y;
                As[lc + 2][lr + rr] = xv.z;
                As[lc + 3][lr + rr] = xv.w;
            }
            float4 wv = *(const float4*)(Wsel + (size_t)(ncol0 + lr + rr) * CC + k0 + lc);
            Bs[lc + 0][lr + rr] = wv.x;
            Bs[lc + 1][lr + rr] = wv.y;
            Bs[lc + 2][lr + rr] = wv.z;
            Bs[lc + 3][lr + rr] = wv.w;
        }
        __syncthreads();
#pragma unroll
        for (int kk = 0; kk < BK; kk++) {
            float a[8], b[8];
            *(float4*)(a)     = *(const float4*)&As[kk][ty * 4];
            *(float4*)(a + 4) = *(const float4*)&As[kk][64 + ty * 4];
            *(float4*)(b)     = *(const float4*)&Bs[kk][tx * 4];
            *(float4*)(b + 4) = *(const float4*)&Bs[kk][64 + tx * 4];
            unsigned long long bp[4];
            bp[0] = pack2(b[0], b[1]);
            bp[1] = pack2(b[2], b[3]);
            bp[2] = pack2(b[4], b[5]);
            bp[3] = pack2(b[6], b[7]);
#pragma unroll
            for (int i = 0; i < 8; i++) {
                unsigned long long ap = pack2(a[i], a[i]);
#pragma unroll
                for (int j = 0; j < 4; j++) ffma2(acc[i][j], ap, bp[j]);
            }
        }
        __syncthreads();
    }

    // epilogue
#pragma unroll
    for (int i = 0; i < 8; i++) {
        int m = m0 + ((i < 4) ? (ty * 4 + i) : (64 + ty * 4 + i - 4));
#pragma unroll
        for (int j = 0; j < 4; j++) {
            int col = ncol0 + ((j < 2) ? (tx * 4 + 2 * j) : (64 + tx * 4 + 2 * (j - 2)));
            float2 v = unpack2(acc[i][j]);
            if (MODE == 1) {
                v.x += bias[col]     + resid[(size_t)m * CC + col];
                v.y += bias[col + 1] + resid[(size_t)m * CC + col + 1];
            }
            *(float2*)(outp + (size_t)m * CC + col) = v;
        }
    }
}

// ---------------- kernel: energy = q . k per (b,h) ----------------
__global__ void __launch_bounds__(256) k_energy() {
    const int bh = blockIdx.x;
    const int b = bh >> 3, h = bh & 7;
    __shared__ float sq[SS * 65];
    __shared__ float sk[SS * 65];
    const int tid = threadIdx.x;
    const float* qp = g_q + (size_t)(b * SS) * CC + h * HD;
    const float* kp = g_k + (size_t)(b * SS) * CC + h * HD;
    for (int idx = tid; idx < SS * HD; idx += 256) {
        int s = idx / HD, d = idx % HD;
        sq[s * 65 + d] = qp[(size_t)s * CC + d];
        sk[s * 65 + d] = kp[(size_t)s * CC + d];
    }
    __syncthreads();
    float* ep = g_energy + (size_t)bh * NPOS;
    for (int p = tid; p < NPOS; p += 256) {
        int i = p / SS, j = p % SS;
        float accv = 0.f;
#pragma unroll
        for (int d = 0; d < HD; d++) accv += sq[i * 65 + d] * sk[j * 65 + d];
        ep[p] = accv;
    }
}

// ---------------- kernel: BN2 position stats over (B,H) ----------------
// grid 256 blocks x 256 threads; each block handles 128 rows of [32768, 961].
__global__ void __launch_bounds__(256) k_bn2_stats() {
    const int tid = threadIdx.x;
    const size_t r0 = (size_t)blockIdx.x * 128;
    const float* ep = g_energy + r0 * NPOS;
    float s[4] = {0.f, 0.f, 0.f, 0.f};
    float q[4] = {0.f, 0.f, 0.f, 0.f};
    for (int r = 0; r < 128; r++) {
        const float* row = ep + (size_t)r * NPOS;
#pragma unroll
        for (int j = 0; j < 4; j++) {
            int col = tid + j * 256;
            if (col < NPOS) {
                float v = row[col];
                s[j] += v; q[j] += v * v;
            }
        }
    }
#pragma unroll
    for (int j = 0; j < 4; j++) {
        int col = tid + j * 256;
        if (col < NPOS) {
            atomicAdd(&g_p_sum[col], s[j]);
            atomicAdd(&g_p_sq[col],  q[j]);
        }
    }
}

__global__ void k_bn2_fin(const float* __restrict__ pw, const float* __restrict__ pb) {
    int i = blockIdx.x * blockDim.x + threadIdx.x;  // <<<4,256>>>
    if (i >= NPOS) return;
    float inv_n = 1.0f / (float)BH;
    float mean = g_p_sum[i] * inv_n;
    float var  = g_p_sq[i] * inv_n - mean * mean;
    float rs   = rsqrtf(var + EPS);
    float a    = rs * pw[i] * INV_SQRT_C;
    g_sc2[i] = a;
    g_sh2[i] = pb[i] * INV_SQRT_C - mean * a;
}

// ---------------- kernel: softmax + attn @ v per (b,h) ----------------
__global__ void __launch_bounds__(256) k_attn() {
    const int bh = blockIdx.x;
    const int b = bh >> 3, h = bh & 7;
    __shared__ float se[SS * 32];
    __shared__ float sv[SS * HD];
    const int tid = threadIdx.x;
    const float* ep = g_energy + (size_t)bh * NPOS;
    for (int p = tid; p < NPOS; p += 256) {
        int i = p / SS, j = p % SS;
        se[i * 32 + j] = fmaf(ep[p], g_sc2[p], g_sh2[p]);
    }
    const float* vp = g_v + (size_t)(b * SS) * CC + h * HD;
    for (int idx = tid; idx < SS * HD; idx += 256) {
        int s = idx / HD, d = idx % HD;
        sv[s * HD + d] = vp[(size_t)s * CC + d];
    }
    __syncthreads();
    // softmax: warp w handles rows w, w+8, w+16, w+24
    const int w = tid >> 5, l = tid & 31;
    for (int r = w; r < SS; r += 8) {
        float val = (l < SS) ? se[r * 32 + l] : -1e30f;
        float mx = val;
#pragma unroll
        for (int off = 16; off > 0; off >>= 1)
            mx = fmaxf(mx, __shfl_xor_sync(0xFFFFFFFFu, mx, off));
        float pe = (l < SS) ? __expf(val - mx) : 0.f;
        float sum = pe;
#pragma unroll
        for (int off = 16; off > 0; off >>= 1)
            sum += __shfl_xor_sync(0xFFFFFFFFu, sum, off);
        if (l < SS) se[r * 32 + l] = pe / sum;
    }
    __syncthreads();
    float* cp = g_ctx + (size_t)(b * SS) * CC + h * HD;
    for (int idx = tid; idx < SS * HD; idx += 256) {
        int i = idx / HD, d = idx % HD;
        float accv = 0.f;
#pragma unroll
        for (int lk = 0; lk < SS; lk++) accv += se[i * 32 + lk] * sv[lk * HD + d];
        cp[(size_t)i * CC + d] = accv;
    }
}

// ---------------- launch ----------------
extern "C" void kernel_launch(void* const* d_in, const int* in_sizes, int n_in,
                              void* d_out, int out_size) {
    const float* x     = (const float*)d_in[0];
    const float* nw    = (const float*)d_in[1];
    const float* nbias = (const float*)d_in[2];
    const float* Wq    = (const float*)d_in[3];
    const float* Wk    = (const float*)d_in[4];
    const float* Wv    = (const float*)d_in[5];
    const float* Wout  = (const float*)d_in[6];
    const float* b_out = (const float*)d_in[7];
    const float* pw    = (const float*)d_in[8];
    const float* pb    = (const float*)d_in[9];
    float* out = (float*)d_out;

    k_zero<<<1, 1024>>>();
    k_bn1_stats<<<M_TOT / 128, 256>>>(x);
    k_bn1_fin<<<2, 256>>>(nw, nbias);

    dim3 gq(3 * CC / BN, M_TOT / BM);   // 12 x 992
    k_gemm<0><<<gq, 256>>>(x, Wq, Wk, Wv, nullptr, nullptr, nullptr);

    k_energy<<<BH, 256>>>();
    k_bn2_stats<<<BH / 128, 256>>>();
    k_bn2_fin<<<4, 256>>>(pw, pb);
    k_attn<<<BH, 256>>>();

    dim3 go(CC / BN, M_TOT / BM);       // 4 x 992
    k_gemm<1><<<go, 256>>>(nullptr, Wout, nullptr, nullptr, b_out, x, out);
}

// round 3
// speedup vs baseline: 2.0956x; 2.0956x over previous
#include <cuda_runtime.h>
#include <cuda_bf16.h>
#include <cstdint>

// Problem constants
#define BB 4096
#define SS 31
#define CC 512
#define HH 8
#define HD 64
#define M_TOT (BB*SS)        // 126976
#define NPOS (SS*SS)         // 961
#define BH (BB*HH)           // 32768
#define EPS 1e-5f
#define INV_SQRT_C 0.044194173824159216f   // 1/sqrt(512)

// ---------------- scratch (static device memory; no allocations) ----------------
// Packed bf16-split layout: per row of 512, 16 chunks; each chunk = 64 bf16 = [32 hi | 32 lo] (128 B).
__device__ __align__(16) __nv_bfloat16 g_xp[(size_t)M_TOT * 1024];
__device__ __align__(16) __nv_bfloat16 g_ctxp[(size_t)M_TOT * 1024];
__device__ __align__(16) __nv_bfloat16 g_wp[(size_t)1536 * 1024];
__device__ __align__(16) __nv_bfloat16 g_wop[(size_t)512 * 1024];

__device__ __align__(16) float g_q[(size_t)M_TOT * CC];
__device__ __align__(16) float g_k[(size_t)M_TOT * CC];
__device__ __align__(16) float g_v[(size_t)M_TOT * CC];
__device__ __align__(16) float g_energy[(size_t)BH * NPOS];

__device__ __align__(16) float g_ch_sum[CC];
__device__ __align__(16) float g_ch_sq[CC];
__device__ __align__(16) float g_scale[CC];
__device__ __align__(16) float g_shift[CC];
__device__ __align__(16) float g_p_sum[NPOS];
__device__ __align__(16) float g_p_sq[NPOS];
__device__ __align__(16) float g_sc2[NPOS];
__device__ __align__(16) float g_sh2[NPOS];

// ---------------- helpers (family-portable: sm_80-era mma/ldmatrix/cp.async) --------
__device__ __forceinline__ uint32_t smem_u32(const void* p) {
    uint32_t a;
    asm("{ .reg .u64 t; cvta.to.shared.u64 t, %1; cvt.u32.u64 %0, t; }" : "=r"(a) : "l"(p));
    return a;
}
__device__ __forceinline__ void cp16(uint32_t dst, const void* src) {
    asm volatile("cp.async.cg.shared.global [%0], [%1], 16;" :: "r"(dst), "l"(src) : "memory");
}
__device__ __forceinline__ void cp_commit() {
    asm volatile("cp.async.commit_group;" ::: "memory");
}
__device__ __forceinline__ void cp_wait1() {
    asm volatile("cp.async.wait_group 1;" ::: "memory");
}
__device__ __forceinline__ void cp_wait0() {
    asm volatile("cp.async.wait_group 0;" ::: "memory");
}
__device__ __forceinline__ void ldsm_x4(uint32_t* r, uint32_t addr) {
    asm volatile("ldmatrix.sync.aligned.m8n8.x4.shared.b16 {%0,%1,%2,%3}, [%4];"
                 : "=r"(r[0]), "=r"(r[1]), "=r"(r[2]), "=r"(r[3]) : "r"(addr));
}
__device__ __forceinline__ void mma16816(float* c, const uint32_t* a, const uint32_t* b) {
    asm volatile(
        "mma.sync.aligned.m16n8k16.row.col.f32.bf16.bf16.f32 "
        "{%0,%1,%2,%3}, {%4,%5,%6,%7}, {%8,%9}, {%0,%1,%2,%3};"
        : "+f"(c[0]), "+f"(c[1]), "+f"(c[2]), "+f"(c[3])
        : "r"(a[0]), "r"(a[1]), "r"(a[2]), "r"(a[3]), "r"(b[0]), "r"(b[1]));
}
#define SWZ(off) ((off) ^ (((off) >> 3) & 0x70u))

// ---------------- kernel: zero reduction buffers ----------------
__global__ void k_zero() {
    int i = threadIdx.x;  // <<<1, 1024>>>
    if (i < CC)   { g_ch_sum[i] = 0.f; g_ch_sq[i] = 0.f; }
    if (i < NPOS) { g_p_sum[i] = 0.f;  g_p_sq[i] = 0.f; }
}

// ---------------- kernel: BN1 channel stats ----------------
__global__ void __launch_bounds__(256) k_bn1_stats(const float* __restrict__ x) {
    const int tid = threadIdx.x;
    const size_t r0 = (size_t)blockIdx.x * 128;
    const float* xp = x + r0 * CC;
    float s0 = 0.f, s1 = 0.f, q0 = 0.f, q1 = 0.f;
    for (int r = 0; r < 128; r++) {
        float v0 = xp[(size_t)r * CC + tid];
        float v1 = xp[(size_t)r * CC + tid + 256];
        s0 += v0; q0 += v0 * v0;
        s1 += v1; q1 += v1 * v1;
    }
    atomicAdd(&g_ch_sum[tid],       s0);
    atomicAdd(&g_ch_sq[tid],        q0);
    atomicAdd(&g_ch_sum[tid + 256], s1);
    atomicAdd(&g_ch_sq[tid + 256],  q1);
}

__global__ void k_bn1_fin(const float* __restrict__ nw, const float* __restrict__ nb) {
    int i = blockIdx.x * blockDim.x + threadIdx.x;  // <<<2,256>>>
    if (i >= CC) return;
    float inv_n = 1.0f / (float)M_TOT;
    float mean = g_ch_sum[i] * inv_n;
    float var  = g_ch_sq[i] * inv_n - mean * mean;
    float rs   = rsqrtf(var + EPS);
    float sc   = rs * nw[i];
    g_scale[i] = sc;
    g_shift[i] = nb[i] - mean * sc;
}

// ---------------- prepass: xn = BN(x), bf16-split, packed ----------------
__global__ void __launch_bounds__(256) k_split_x(const float* __restrict__ x) {
    size_t t = (size_t)blockIdx.x * 256 + threadIdx.x;  // M_TOT*64 threads, 8 elems each
    size_t m = t >> 6;
    int oct = (int)(t & 63);
    int c = oct >> 2, pos = (oct & 3) << 3, k = oct << 3;
    const float* xp = x + m * 512 + k;
    float4 a  = *(const float4*)xp;
    float4 b  = *(const float4*)(xp + 4);
    float4 sA = *(const float4*)(g_scale + k);
    float4 sB = *(const float4*)(g_scale + k + 4);
    float4 hA = *(const float4*)(g_shift + k);
    float4 hB = *(const float4*)(g_shift + k + 4);
    float v[8];
    v[0] = fmaf(a.x, sA.x, hA.x); v[1] = fmaf(a.y, sA.y, hA.y);
    v[2] = fmaf(a.z, sA.z, hA.z); v[3] = fmaf(a.w, sA.w, hA.w);
    v[4] = fmaf(b.x, sB.x, hB.x); v[5] = fmaf(b.y, sB.y, hB.y);
    v[6] = fmaf(b.z, sB.z, hB.z); v[7] = fmaf(b.w, sB.w, hB.w);
    __nv_bfloat16 hi[8], lo[8];
#pragma unroll
    for (int i = 0; i < 8; i++) {
        hi[i] = __float2bfloat16(v[i]);
        lo[i] = __float2bfloat16(v[i] - __bfloat162float(hi[i]));
    }
    __nv_bfloat16* dst = g_xp + ((m * 16 + c) << 6) + pos;
    *(uint4*)dst        = *(uint4*)hi;
    *(uint4*)(dst + 32) = *(uint4*)lo;
}

// ---------------- prepass: weights bf16-split, packed ----------------
__global__ void __launch_bounds__(256) k_split_w(const float* __restrict__ Wq,
                                                 const float* __restrict__ Wk,
                                                 const float* __restrict__ Wv,
                                                 const float* __restrict__ Wo) {
    int t = blockIdx.x * 256 + threadIdx.x;  // (1536+512)*64 threads
    int row = t >> 6;
    int oct = t & 63;
    int c = oct >> 2, pos = (oct & 3) << 3, k = oct << 3;
    const float* src;
    __nv_bfloat16* dst;
    if (row < 1536) {
        src = (row < 512) ? (Wq + (size_t)row * 512)
            : (row < 1024) ? (Wk + (size_t)(row - 512) * 512)
                           : (Wv + (size_t)(row - 1024) * 512);
        dst = g_wp + (((size_t)row * 16 + c) << 6) + pos;
    } else {
        int r2 = row - 1536;
        src = Wo + (size_t)r2 * 512;
        dst = g_wop + (((size_t)r2 * 16 + c) << 6) + pos;
    }
    float4 a = *(const float4*)(src + k);
    float4 b = *(const float4*)(src + k + 4);
    float v[8] = {a.x, a.y, a.z, a.w, b.x, b.y, b.z, b.w};
    __nv_bfloat16 hi[8], lo[8];
#pragma unroll
    for (int i = 0; i < 8; i++) {
        hi[i] = __float2bfloat16(v[i]);
        lo[i] = __float2bfloat16(v[i] - __bfloat162float(hi[i]));
    }
    *(uint4*)dst        = *(uint4*)hi;
    *(uint4*)(dst + 32) = *(uint4*)lo;
}

// ---------------- HMMA GEMM: CTA 128x128, 4 warps (64x64 each), 3-term bf16 ----------
// MODE 0: A=g_xp, B=g_wp (1536 rows) -> writes g_q/g_k/g_v fp32
// MODE 1: A=g_ctxp, B=g_wop (512 rows) -> out = D + bias + resid
template<int MODE>
__global__ void __launch_bounds__(128) k_mma_gemm(const float* __restrict__ bias,
                                                  const float* __restrict__ resid,
                                                  float* __restrict__ Dout) {
    extern __shared__ char sm[];  // 2 stages x (A 16KB + B 16KB) = 64KB
    const int tid = threadIdx.x, lane = tid & 31, w = tid >> 5;
    const int wm = w >> 1, wn = w & 1;
    const int m0 = blockIdx.y * 128, n0g = blockIdx.x * 128;
    const __nv_bfloat16* Asrc = (MODE == 0) ? g_xp : g_ctxp;
    const __nv_bfloat16* Bsrc = (MODE == 0) ? g_wp : g_wop;
    const uint32_t sbase = smem_u32(sm);

    float c[4][8][4];
#pragma unroll
    for (int i = 0; i < 4; i++)
#pragma unroll
        for (int j = 0; j < 8; j++)
#pragma unroll
            for (int l = 0; l < 4; l++) c[i][j][l] = 0.f;

    // lane addressing for ldmatrix
    const int a_row = lane & 15;                 // A: rows 0-15, halves by lane>>4
    const int a_cb  = (lane >> 4) * 16;
    const int b_row = (lane & 7) + ((lane >> 4) & 1) * 8;   // B: n-row
    const int b_cb  = ((lane >> 3) & 1) * 16;

    // --- stage loader ---
    auto load_stage = [&](int st, int ch) {
        uint32_t abase = sbase + st * 32768;
        uint32_t bbase = abase + 16384;
#pragma unroll
        for (int j = 0; j < 8; j++) {
            int u = j * 128 + tid, r = u >> 3, q = u & 7;
            cp16(abase + SWZ((uint32_t)(r * 128 + q * 16)),
                 Asrc + (((size_t)(m0 + r) * 16 + ch) << 6) + q * 8);
        }
#pragma unroll
        for (int j = 0; j < 8; j++) {
            int u = j * 128 + tid, r = u >> 3, q = u & 7;
            cp16(bbase + SWZ((uint32_t)(r * 128 + q * 16)),
                 Bsrc + (((size_t)(n0g + r) * 16 + ch) << 6) + q * 8);
        }
        cp_commit();
    };

    load_stage(0, 0);

    for (int it = 0; it < 16; it++) {
        if (it + 1 < 16) { load_stage((it + 1) & 1, it + 1); cp_wait1(); }
        else             { cp_wait0(); }
        __syncthreads();

        const uint32_t abase = sbase + (it & 1) * 32768;
        const uint32_t bbase = abase + 16384;

#pragma unroll
        for (int ks = 0; ks < 2; ks++) {
            uint32_t ah[16], al[16], bh[16], bl[16];
            // hi A fragments (4 m16 tiles)
#pragma unroll
            for (int mi = 0; mi < 4; mi++)
                ldsm_x4(&ah[mi * 4],
                        abase + SWZ((uint32_t)((wm * 64 + mi * 16 + a_row) * 128 + ks * 32 + a_cb)));
            // hi B fragments (4 x4 covering 64 n)
#pragma unroll
            for (int nt = 0; nt < 4; nt++)
                ldsm_x4(&bh[nt * 4],
                        bbase + SWZ((uint32_t)((wn * 64 + nt * 16 + b_row) * 128 + ks * 32 + b_cb)));
            // term 1: hiA x hiB
#pragma unroll
            for (int mi = 0; mi < 4; mi++)
#pragma unroll
                for (int nj = 0; nj < 8; nj++)
                    mma16816(c[mi][nj], &ah[mi * 4], &bh[nj * 2]);
            // lo B
#pragma unroll
            for (int nt = 0; nt < 4; nt++)
                ldsm_x4(&bl[nt * 4],
                        bbase + SWZ((uint32_t)((wn * 64 + nt * 16 + b_row) * 128 + 64 + ks * 32 + b_cb)));
            // term 2: hiA x loB
#pragma unroll
            for (int mi = 0; mi < 4; mi++)
#pragma unroll
                for (int nj = 0; nj < 8; nj++)
                    mma16816(c[mi][nj], &ah[mi * 4], &bl[nj * 2]);
            // lo A
#pragma unroll
            for (int mi = 0; mi < 4; mi++)
                ldsm_x4(&al[mi * 4],
                        abase + SWZ((uint32_t)((wm * 64 + mi * 16 + a_row) * 128 + 64 + ks * 32 + a_cb)));
            // term 3: loA x hiB
#pragma unroll
            for (int mi = 0; mi < 4; mi++)
#pragma unroll
                for (int nj = 0; nj < 8; nj++)
                    mma16816(c[mi][nj], &al[mi * 4], &bh[nj * 2]);
        }
        __syncthreads();
    }

    // ---------------- epilogue: register fragments -> global ----------------
    const int r1 = lane >> 2;
    const int c0 = (lane & 3) * 2;
#pragma unroll
    for (int mi = 0; mi < 4; mi++) {
        const int gr = m0 + wm * 64 + mi * 16;
#pragma unroll
        for (int nj = 0; nj < 8; nj++) {
            const int gc = n0g + wn * 64 + nj * 8 + c0;
            if (MODE == 0) {
                const int sel = gc >> 9;
                const int col = gc & 511;
                float* op = (sel == 0) ? g_q : ((sel == 1) ? g_k : g_v);
                *(float2*)(op + (size_t)(gr + r1) * 512 + col) =
                    make_float2(c[mi][nj][0], c[mi][nj][1]);
                *(float2*)(op + (size_t)(gr + r1 + 8) * 512 + col) =
                    make_float2(c[mi][nj][2], c[mi][nj][3]);
            } else {
                const int col = gc;
                const float b0 = bias[col], b1 = bias[col + 1];
                {
                    const size_t off = (size_t)(gr + r1) * 512 + col;
                    float2 rv = *(const float2*)(resid + off);
                    *(float2*)(Dout + off) =
                        make_float2(c[mi][nj][0] + b0 + rv.x, c[mi][nj][1] + b1 + rv.y);
                }
                {
                    const size_t off = (size_t)(gr + r1 + 8) * 512 + col;
                    float2 rv = *(const float2*)(resid + off);
                    *(float2*)(Dout + off) =
                        make_float2(c[mi][nj][2] + b0 + rv.x, c[mi][nj][3] + b1 + rv.y);
                }
            }
        }
    }
}

// ---------------- kernel: energy = q . k per (b,h) ----------------
__global__ void __launch_bounds__(256) k_energy() {
    const int bh = blockIdx.x;
    const int b = bh >> 3, h = bh & 7;
    __shared__ float sq[SS * 65];
    __shared__ float sk[SS * 65];
    const int tid = threadIdx.x;
    const float* qp = g_q + (size_t)(b * SS) * CC + h * HD;
    const float* kp = g_k + (size_t)(b * SS) * CC + h * HD;
    for (int idx = tid; idx < SS * HD; idx += 256) {
        int s = idx / HD, d = idx % HD;
        sq[s * 65 + d] = qp[(size_t)s * CC + d];
        sk[s * 65 + d] = kp[(size_t)s * CC + d];
    }
    __syncthreads();
    float* ep = g_energy + (size_t)bh * NPOS;
    for (int p = tid; p < NPOS; p += 256) {
        int i = p / SS, j = p % SS;
        float accv = 0.f;
#pragma unroll
        for (int d = 0; d < HD; d++) accv += sq[i * 65 + d] * sk[j * 65 + d];
        ep[p] = accv;
    }
}

// ---------------- kernel: BN2 position stats over (B,H) ----------------
__global__ void __launch_bounds__(256) k_bn2_stats() {
    const int tid = threadIdx.x;
    const size_t r0 = (size_t)blockIdx.x * 128;
    const float* ep = g_energy + r0 * NPOS;
    float s[4] = {0.f, 0.f, 0.f, 0.f};
    float q[4] = {0.f, 0.f, 0.f, 0.f};
    for (int r = 0; r < 128; r++) {
        const float* row = ep + (size_t)r * NPOS;
#pragma unroll
        for (int j = 0; j < 4; j++) {
            int col = tid + j * 256;
            if (col < NPOS) {
                float v = row[col];
                s[j] += v; q[j] += v * v;
            }
        }
    }
#pragma unroll
    for (int j = 0; j < 4; j++) {
        int col = tid + j * 256;
        if (col < NPOS) {
            atomicAdd(&g_p_sum[col], s[j]);
            atomicAdd(&g_p_sq[col],  q[j]);
        }
    }
}

__global__ void k_bn2_fin(const float* __restrict__ pw, const float* __restrict__ pb) {
    int i = blockIdx.x * blockDim.x + threadIdx.x;  // <<<4,256>>>
    if (i >= NPOS) return;
    float inv_n = 1.0f / (float)BH;
    float mean = g_p_sum[i] * inv_n;
    float var  = g_p_sq[i] * inv_n - mean * mean;
    float rs   = rsqrtf(var + EPS);
    float a    = rs * pw[i] * INV_SQRT_C;
    g_sc2[i] = a;
    g_sh2[i] = pb[i] * INV_SQRT_C - mean * a;
}

// ---------------- kernel: softmax + attn @ v per (b,h); writes split ctx ----------------
__global__ void __launch_bounds__(256) k_attn() {
    const int bh = blockIdx.x;
    const int b = bh >> 3, h = bh & 7;
    __shared__ float se[SS * 32];
    __shared__ float sv[SS * HD];
    const int tid = threadIdx.x;
    const float* ep = g_energy + (size_t)bh * NPOS;
    for (int p = tid; p < NPOS; p += 256) {
        int i = p / SS, j = p % SS;
        se[i * 32 + j] = fmaf(ep[p], g_sc2[p], g_sh2[p]);
    }
    const float* vp = g_v + (size_t)(b * SS) * CC + h * HD;
    for (int idx = tid; idx < SS * HD; idx += 256) {
        int s = idx / HD, d = idx % HD;
        sv[s * HD + d] = vp[(size_t)s * CC + d];
    }
    __syncthreads();
    const int w = tid >> 5, l = tid & 31;
    for (int r = w; r < SS; r += 8) {
        float val = (l < SS) ? se[r * 32 + l] : -1e30f;
        float mx = val;
#pragma unroll
        for (int off = 16; off > 0; off >>= 1)
            mx = fmaxf(mx, __shfl_xor_sync(0xFFFFFFFFu, mx, off));
        float pe = (l < SS) ? __expf(val - mx) : 0.f;
        float sum = pe;
#pragma unroll
        for (int off = 16; off > 0; off >>= 1)
            sum += __shfl_xor_sync(0xFFFFFFFFu, sum, off);
        if (l < SS) se[r * 32 + l] = pe / sum;
    }
    __syncthreads();
    for (int idx = tid; idx < SS * HD; idx += 256) {
        int i = idx / HD, d = idx % HD;
        float accv = 0.f;
#pragma unroll
        for (int lk = 0; lk < SS; lk++) accv += se[i * 32 + lk] * sv[lk * HD + d];
        __nv_bfloat16 hi = __float2bfloat16(accv);
        __nv_bfloat16 lo = __float2bfloat16(accv - __bfloat162float(hi));
        int colg = h * HD + d;
        int c = colg >> 5, pos = colg & 31;
        size_t base = (((size_t)(b * SS + i) * 16 + c) << 6) + pos;
        g_ctxp[base]      = hi;
        g_ctxp[base + 32] = lo;
    }
}

// ---------------- launch ----------------
extern "C" void kernel_launch(void* const* d_in, const int* in_sizes, int n_in,
                              void* d_out, int out_size) {
    const float* x     = (const float*)d_in[0];
    const float* nw    = (const float*)d_in[1];
    const float* nbias = (const float*)d_in[2];
    const float* Wq    = (const float*)d_in[3];
    const float* Wk    = (const float*)d_in[4];
    const float* Wv    = (const float*)d_in[5];
    const float* Wout  = (const float*)d_in[6];
    const float* b_out = (const float*)d_in[7];
    const float* pw    = (const float*)d_in[8];
    const float* pb    = (const float*)d_in[9];
    float* out = (float*)d_out;

    cudaFuncSetAttribute(k_mma_gemm<0>, cudaFuncAttributeMaxDynamicSharedMemorySize, 65536);
    cudaFuncSetAttribute(k_mma_gemm<1>, cudaFuncAttributeMaxDynamicSharedMemorySize, 65536);

    k_zero<<<1, 1024>>>();
    k_split_w<<<512, 256>>>(Wq, Wk, Wv, Wout);
    k_bn1_stats<<<M_TOT / 128, 256>>>(x);
    k_bn1_fin<<<2, 256>>>(nw, nbias);
    k_split_x<<<M_TOT / 4, 256>>>(x);

    k_mma_gemm<0><<<dim3(12, 992), 128, 65536>>>(nullptr, nullptr, nullptr);

    k_energy<<<BH, 256>>>();
    k_bn2_stats<<<BH / 128, 256>>>();
    k_bn2_fin<<<4, 256>>>(pw, pb);
    k_attn<<<BH, 256>>>();

    k_mma_gemm<1><<<dim3(4, 992), 128, 65536>>>(b_out, x, out);
}